// round 13
// baseline (speedup 1.0000x reference)
#include <cuda_runtime.h>
#include <cuda_bf16.h>
#include <cstdint>

#define KK 64
#define NN 4096
#define MTILE 128
#define KC 64                          // n-elements per chunk
#define KSPLIT 8
#define NCHUNK ((NN / KSPLIT) / KC)    // 8
#define SROWB 144                      // smem row stride in bytes (72 bf16)
#define NTILES (NN / MTILE)            // 32 i-tiles

#define XTILE_B (MTILE * SROWB)        // 18432
#define ZTILE_B (KK * SROWB)           // 9216
#define SMEM_TOT (2 * XTILE_B + 2 * ZTILE_B)  // 55296

// Partial row_sums: [KSPLIT][KK][NN] fp32 = 8 MB
__device__ float g_partial[KSPLIT * KK * NN];
__device__ int   g_counter[NTILES];

static __device__ __forceinline__ uint32_t smem_u32(const void* p) {
    uint32_t a;
    asm("{ .reg .u64 t; cvta.to.shared.u64 t, %1; cvt.u32.u64 %0, t; }"
        : "=r"(a) : "l"(p));
    return a;
}
static __device__ __forceinline__ uint32_t pack2(float a, float b) {
    __nv_bfloat162 h = __floats2bfloat162_rn(a, b);
    return *reinterpret_cast<uint32_t*>(&h);
}
static __device__ __forceinline__ void sts128(uint32_t a, uint32_t x, uint32_t y,
                                              uint32_t z, uint32_t w) {
    asm volatile("st.shared.v4.b32 [%0], {%1,%2,%3,%4};"
                 :: "r"(a), "r"(x), "r"(y), "r"(z), "r"(w) : "memory");
}
static __device__ __forceinline__ void ldsm4(uint32_t addr, uint32_t& r0, uint32_t& r1,
                                             uint32_t& r2, uint32_t& r3) {
    asm volatile("ldmatrix.sync.aligned.m8n8.x4.shared.b16 {%0,%1,%2,%3}, [%4];"
                 : "=r"(r0), "=r"(r1), "=r"(r2), "=r"(r3) : "r"(addr));
}
static __device__ __forceinline__ void mma16816(float& c0, float& c1, float& c2, float& c3,
                                                uint32_t a0, uint32_t a1, uint32_t a2,
                                                uint32_t a3, uint32_t b0, uint32_t b1) {
    asm volatile("mma.sync.aligned.m16n8k16.row.col.f32.bf16.bf16.f32 "
                 "{%0,%1,%2,%3}, {%4,%5,%6,%7}, {%8,%9}, {%0,%1,%2,%3};"
                 : "+f"(c0), "+f"(c1), "+f"(c2), "+f"(c3)
                 : "r"(a0), "r"(a1), "r"(a2), "r"(a3), "r"(b0), "r"(b1));
}

// ---------------------------------------------------------------------------
// zero: out + tile counters (runs before gemm each graph replay)
// ---------------------------------------------------------------------------
__global__ void zero_kernel(float* out) {
    if (threadIdx.x == 0) out[0] = 0.f;
    if (threadIdx.x < NTILES) g_counter[threadIdx.x] = 0;
}

// ---------------------------------------------------------------------------
// HMMA GEMM + fused finish.
// grid = (32, KSPLIT) = 256 CTAs, block = 256 (8 warps: 4 i-groups x 2 k-groups)
// KC=64 chunks, distance-1 register staging, double-buffered smem tiles.
// Last split-CTA per i-tile folds partials into the scalar loss.
// ---------------------------------------------------------------------------
__global__ __launch_bounds__(256, 2)
void gemm_hmma(const float* __restrict__ zs, const float* __restrict__ X,
               const float* __restrict__ vn_p, float* __restrict__ out) {
    extern __shared__ __align__(16) char dsm[];
    const uint32_t base = smem_u32(dsm);
    const uint32_t XsA[2] = { base, base + XTILE_B };
    const uint32_t ZsA[2] = { base + 2 * XTILE_B, base + 2 * XTILE_B + ZTILE_B };

    const int tid   = threadIdx.x;
    const int lane  = tid & 31;
    const int wid   = tid >> 5;
    const int ibase = blockIdx.x * MTILE;
    const int nbase = blockIdx.y * (NN / KSPLIT);

    // ---- X producer: 2 threads/row, 32 consecutive floats each ----
    const int xrow  = tid >> 1;
    const int xhalf = (tid & 1) * 32;               // n offset (floats)
    const float* xp = X + (size_t)(ibase + xrow) * NN + nbase + xhalf;
    const uint32_t xsto = xrow * SROWB + xhalf * 2; // bf16 bytes

    // ---- zs producer: 4 threads/row, 16 consecutive floats each ----
    const int zrow = tid >> 2;
    const int zoff = (tid & 3) * 16;
    const float* zp = zs + (size_t)zrow * NN + nbase + zoff;
    const uint32_t zsto = zrow * SROWB + zoff * 2;

    // ---- consumer (ldmatrix) address components ----
    const int wi = (wid & 3) * 32;
    const int wj = (wid >> 2) * 32;
    const uint32_t a_row = wi + (lane & 15);
    const uint32_t a_col16 = (lane >> 4);
    const uint32_t b_row = wj + ((lane >> 4) & 1) * 8 + (lane & 7);
    const uint32_t b_col16 = ((lane >> 3) & 1);

    float acc[2][4][4];
#pragma unroll
    for (int m = 0; m < 2; ++m)
#pragma unroll
        for (int n = 0; n < 4; ++n)
#pragma unroll
            for (int q = 0; q < 4; ++q) acc[m][n][q] = 0.f;

#define LOAD_ALL(xr, zr, off)                                              \
    do {                                                                   \
        _Pragma("unroll")                                                  \
        for (int j = 0; j < 8; ++j) xr[j] = *(const float4*)(xp + (off) + j * 4); \
        _Pragma("unroll")                                                  \
        for (int j = 0; j < 4; ++j) zr[j] = *(const float4*)(zp + (off) + j * 4); \
    } while (0)

#define STS_ALL(buf, xr, zr)                                                         \
    do {                                                                             \
        _Pragma("unroll")                                                            \
        for (int j = 0; j < 4; ++j)                                                  \
            sts128(XsA[buf] + xsto + j * 16,                                         \
                   pack2(xr[2*j].x, xr[2*j].y),   pack2(xr[2*j].z, xr[2*j].w),       \
                   pack2(xr[2*j+1].x, xr[2*j+1].y), pack2(xr[2*j+1].z, xr[2*j+1].w));\
        _Pragma("unroll")                                                            \
        for (int j = 0; j < 2; ++j)                                                  \
            sts128(ZsA[buf] + zsto + j * 16,                                         \
                   pack2(zr[2*j].x, zr[2*j].y),   pack2(zr[2*j].z, zr[2*j].w),       \
                   pack2(zr[2*j+1].x, zr[2*j+1].y), pack2(zr[2*j+1].z, zr[2*j+1].w));\
    } while (0)

#define MMA_PHASE(buf)                                                              \
    do {                                                                            \
        _Pragma("unroll")                                                           \
        for (int s = 0; s < 4; ++s) {                                               \
            uint32_t a[2][4], b[2][4];                                              \
            _Pragma("unroll")                                                       \
            for (int h = 0; h < 2; ++h)                                             \
                ldsm4(XsA[buf] + (a_row + h * 16) * SROWB + (a_col16 + s * 2) * 16, \
                      a[h][0], a[h][1], a[h][2], a[h][3]);                          \
            _Pragma("unroll")                                                       \
            for (int g = 0; g < 2; ++g)                                             \
                ldsm4(ZsA[buf] + (b_row + g * 16) * SROWB + (b_col16 + s * 2) * 16, \
                      b[g][0], b[g][1], b[g][2], b[g][3]);                          \
            _Pragma("unroll")                                                       \
            for (int m = 0; m < 2; ++m)                                             \
                _Pragma("unroll")                                                   \
                for (int n = 0; n < 4; ++n) {                                       \
                    const int g = n >> 1, hi = (n & 1) * 2;                         \
                    mma16816(acc[m][n][0], acc[m][n][1], acc[m][n][2],              \
                             acc[m][n][3], a[m][0], a[m][1], a[m][2], a[m][3],      \
                             b[g][hi], b[g][hi + 1]);                               \
                }                                                                   \
        }                                                                           \
    } while (0)

    float4 xr[8], zr[4];
    LOAD_ALL(xr, zr, 0);

#pragma unroll 1
    for (int c = 0; c < NCHUNK; ++c) {
        const int buf = c & 1;
        STS_ALL(buf, xr, zr);
        __syncthreads();   // tiles(c) ready; also orders MMA(c-1) before STS(c+1)
        if (c + 1 < NCHUNK) LOAD_ALL(xr, zr, (c + 1) * KC);
        MMA_PHASE(buf);
    }

    // ---- epilogue: write warp tile to g_partial[by][j][i] ----
    float* part = g_partial + (size_t)blockIdx.y * (KK * NN);
#pragma unroll
    for (int m = 0; m < 2; ++m) {
        const int i0 = ibase + wi + m * 16 + (lane >> 2);
#pragma unroll
        for (int n = 0; n < 4; ++n) {
            const int j0 = wj + n * 8 + (lane & 3) * 2;
            part[(size_t)j0 * NN + i0]           = acc[m][n][0];
            part[(size_t)(j0 + 1) * NN + i0]     = acc[m][n][1];
            part[(size_t)j0 * NN + i0 + 8]       = acc[m][n][2];
            part[(size_t)(j0 + 1) * NN + i0 + 8] = acc[m][n][3];
        }
    }

    // ---- fused finish: last split-CTA of this i-tile folds the loss ----
    __shared__ int s_last;
    __threadfence();                       // release partial stores
    __syncthreads();
    if (tid == 0) s_last = atomicAdd(&g_counter[blockIdx.x], 1);
    __syncthreads();
    if (s_last == KSPLIT - 1) {
        __threadfence();                   // acquire others' partial stores
        const float vn = *vn_p;
        float local = 0.f;
#pragma unroll 4
        for (int j = 0; j < (KK * MTILE) / 256; ++j) {   // 32 elems/thread
            const int e  = tid + j * 256;                // 0..8191
            const int k  = e >> 7;
            const int i  = ibase + (e & 127);
            float rs = 0.f;
#pragma unroll
            for (int s = 0; s < KSPLIT; ++s)
                rs += g_partial[(size_t)s * (KK * NN) + (size_t)k * NN + i];
            const float z   = zs[(size_t)k * NN + i];
            const float xd  = X[(size_t)i * NN + i];
            const float num = z * xd;
            local += num / (vn + rs - num);
        }
#pragma unroll
        for (int off = 16; off > 0; off >>= 1)
            local += __shfl_down_sync(0xffffffffu, local, off);
        __shared__ float red[8];
        if (lane == 0) red[wid] = local;
        __syncthreads();
        if (wid == 0) {
            float v = (lane < 8) ? red[lane] : 0.f;
#pragma unroll
            for (int off = 4; off > 0; off >>= 1)
                v += __shfl_down_sync(0xffffffffu, v, off);
            if (lane == 0) atomicAdd(out, -v / (float)KK);
        }
    }
}

// ---------------------------------------------------------------------------
extern "C" void kernel_launch(void* const* d_in, const int* in_sizes, int n_in,
                              void* d_out, int out_size) {
    const float* zs = (const float*)d_in[0];   // [64, 4096]
    const float* X  = (const float*)d_in[1];   // [4096, 4096]
    const float* vn = (const float*)d_in[2];   // scalar
    float* out = (float*)d_out;

    cudaFuncSetAttribute(gemm_hmma, cudaFuncAttributeMaxDynamicSharedMemorySize,
                         SMEM_TOT);

    zero_kernel<<<1, 64>>>(out);
    dim3 grid(NTILES, KSPLIT);                 // 32 x 8 = 256 CTAs
    gemm_hmma<<<grid, 256, SMEM_TOT>>>(zs, X, vn, out);
}

// round 14
// speedup vs baseline: 1.3279x; 1.3279x over previous
#include <cuda_runtime.h>
#include <cuda_bf16.h>
#include <cstdint>

#define KK 64
#define NN 4096
#define MTILE 128
#define KC 32                          // n-elements per chunk
#define KSPLIT 8
#define NCHUNK ((NN / KSPLIT) / KC)    // 16 (even)
#define SROW 40                        // smem row stride in bf16 elems (80 B)
#define NTILES (NN / MTILE)            // 32 i-tiles

// Partial row_sums: [KSPLIT][KK][NN] fp32 = 8 MB
__device__ float g_partial[KSPLIT * KK * NN];
__device__ int   g_counter[NTILES];

static __device__ __forceinline__ uint32_t smem_u32(const void* p) {
    uint32_t a;
    asm("{ .reg .u64 t; cvta.to.shared.u64 t, %1; cvt.u32.u64 %0, t; }"
        : "=r"(a) : "l"(p));
    return a;
}
static __device__ __forceinline__ uint32_t pack2(float a, float b) {
    __nv_bfloat162 h = __floats2bfloat162_rn(a, b);
    return *reinterpret_cast<uint32_t*>(&h);
}
static __device__ __forceinline__ void sts128(uint32_t a, uint32_t x, uint32_t y,
                                              uint32_t z, uint32_t w) {
    asm volatile("st.shared.v4.b32 [%0], {%1,%2,%3,%4};"
                 :: "r"(a), "r"(x), "r"(y), "r"(z), "r"(w) : "memory");
}
static __device__ __forceinline__ void ldsm4(uint32_t addr, uint32_t& r0, uint32_t& r1,
                                             uint32_t& r2, uint32_t& r3) {
    asm volatile("ldmatrix.sync.aligned.m8n8.x4.shared.b16 {%0,%1,%2,%3}, [%4];"
                 : "=r"(r0), "=r"(r1), "=r"(r2), "=r"(r3) : "r"(addr));
}
static __device__ __forceinline__ void mma16816(float& c0, float& c1, float& c2, float& c3,
                                                uint32_t a0, uint32_t a1, uint32_t a2,
                                                uint32_t a3, uint32_t b0, uint32_t b1) {
    asm volatile("mma.sync.aligned.m16n8k16.row.col.f32.bf16.bf16.f32 "
                 "{%0,%1,%2,%3}, {%4,%5,%6,%7}, {%8,%9}, {%0,%1,%2,%3};"
                 : "+f"(c0), "+f"(c1), "+f"(c2), "+f"(c3)
                 : "r"(a0), "r"(a1), "r"(a2), "r"(a3), "r"(b0), "r"(b1));
}

// ---------------------------------------------------------------------------
// zero: out + tile counters (runs before gemm each graph replay)
// ---------------------------------------------------------------------------
__global__ void zero_kernel(float* out) {
    if (threadIdx.x == 0) out[0] = 0.f;
    if (threadIdx.x < NTILES) g_counter[threadIdx.x] = 0;
}

// ---------------------------------------------------------------------------
// HMMA GEMM + fused finish: g_partial[by][k][i] = sum_{n in split} zs[k][n]*X[i][n]
// grid = (32, KSPLIT) = 256 CTAs, block = 256 (8 warps: 4 i-groups x 2 k-groups)
// Mainloop identical to R11 (KC=32, distance-2 A/B staging, 1 barrier/chunk).
// Last split-CTA per i-tile folds its 128x64 slice into the scalar loss.
// ---------------------------------------------------------------------------
__global__ __launch_bounds__(256, 2)
void gemm_hmma(const float* __restrict__ zs, const float* __restrict__ X,
               const float* __restrict__ vn_p, float* __restrict__ out) {
    __shared__ __align__(16) __nv_bfloat16 Xs[2][MTILE * SROW];
    __shared__ __align__(16) __nv_bfloat16 Zs[2][KK * SROW];

    const int tid   = threadIdx.x;
    const int lane  = tid & 31;
    const int wid   = tid >> 5;
    const int ibase = blockIdx.x * MTILE;
    const int nbase = blockIdx.y * (NN / KSPLIT);

    const uint32_t XsA[2] = { smem_u32(Xs[0]), smem_u32(Xs[1]) };
    const uint32_t ZsA[2] = { smem_u32(Zs[0]), smem_u32(Zs[1]) };

    // ---- producer assignments (8-float units) ----
    const int xu0 = tid, xu1 = tid + 256;
    const int xrow0 = xu0 >> 2, xqc0 = xu0 & 3;
    const int xrow1 = xu1 >> 2, xqc1 = xu1 & 3;
    const float* xp0 = X + (size_t)(ibase + xrow0) * NN + nbase + xqc0 * 8;
    const float* xp1 = X + (size_t)(ibase + xrow1) * NN + nbase + xqc1 * 8;
    const uint32_t xs0 = xrow0 * (SROW * 2) + xqc0 * 16;
    const uint32_t xs1 = xrow1 * (SROW * 2) + xqc1 * 16;
    const int zrow = tid >> 2, zqc = tid & 3;
    const float* zp = zs + (size_t)zrow * NN + nbase + zqc * 8;
    const uint32_t zsto = zrow * (SROW * 2) + zqc * 16;

    // ---- consumer (ldmatrix) address components ----
    const int wi = (wid & 3) * 32;
    const int wj = (wid >> 2) * 32;
    const uint32_t a_row = wi + (lane & 15);
    const uint32_t a_col16 = (lane >> 4);
    const uint32_t b_row = wj + ((lane >> 4) & 1) * 8 + (lane & 7);
    const uint32_t b_col16 = ((lane >> 3) & 1);

    float acc[2][4][4];
#pragma unroll
    for (int m = 0; m < 2; ++m)
#pragma unroll
        for (int n = 0; n < 4; ++n)
#pragma unroll
            for (int q = 0; q < 4; ++q) acc[m][n][q] = 0.f;

#define LOAD_SET(xr, zr, off)                                              \
    do {                                                                   \
        xr[0] = *(const float4*)(xp0 + (off));                             \
        xr[1] = *(const float4*)(xp0 + (off) + 4);                         \
        xr[2] = *(const float4*)(xp1 + (off));                             \
        xr[3] = *(const float4*)(xp1 + (off) + 4);                         \
        zr[0] = *(const float4*)(zp + (off));                              \
        zr[1] = *(const float4*)(zp + (off) + 4);                          \
    } while (0)

#define STS_SET(buf, xr, zr)                                                        \
    do {                                                                            \
        sts128(XsA[buf] + xs0, pack2(xr[0].x, xr[0].y), pack2(xr[0].z, xr[0].w),    \
               pack2(xr[1].x, xr[1].y), pack2(xr[1].z, xr[1].w));                   \
        sts128(XsA[buf] + xs1, pack2(xr[2].x, xr[2].y), pack2(xr[2].z, xr[2].w),    \
               pack2(xr[3].x, xr[3].y), pack2(xr[3].z, xr[3].w));                   \
        sts128(ZsA[buf] + zsto, pack2(zr[0].x, zr[0].y), pack2(zr[0].z, zr[0].w),   \
               pack2(zr[1].x, zr[1].y), pack2(zr[1].z, zr[1].w));                   \
    } while (0)

#define MMA_PHASE(buf)                                                              \
    do {                                                                            \
        _Pragma("unroll")                                                           \
        for (int s = 0; s < 2; ++s) {                                               \
            uint32_t a[2][4], b[2][4];                                              \
            _Pragma("unroll")                                                       \
            for (int h = 0; h < 2; ++h)                                             \
                ldsm4(XsA[buf] + (a_row + h * 16) * (SROW * 2) +                    \
                          (a_col16 + s * 2) * 16,                                   \
                      a[h][0], a[h][1], a[h][2], a[h][3]);                          \
            _Pragma("unroll")                                                       \
            for (int g = 0; g < 2; ++g)                                             \
                ldsm4(ZsA[buf] + (b_row + g * 16) * (SROW * 2) +                    \
                          (b_col16 + s * 2) * 16,                                   \
                      b[g][0], b[g][1], b[g][2], b[g][3]);                          \
            _Pragma("unroll")                                                       \
            for (int m = 0; m < 2; ++m)                                             \
                _Pragma("unroll")                                                   \
                for (int n = 0; n < 4; ++n) {                                       \
                    const int g = n >> 1, hi = (n & 1) * 2;                         \
                    mma16816(acc[m][n][0], acc[m][n][1], acc[m][n][2],              \
                             acc[m][n][3], a[m][0], a[m][1], a[m][2], a[m][3],      \
                             b[g][hi], b[g][hi + 1]);                               \
                }                                                                   \
        }                                                                           \
    } while (0)

    // prologue: stage chunks 0 (set A) and 1 (set B)
    float4 xrA[4], zrA[2], xrB[4], zrB[2];
    LOAD_SET(xrA, zrA, 0);
    LOAD_SET(xrB, zrB, KC);

#pragma unroll 1
    for (int c = 0; c < NCHUNK; c += 2) {
        // even chunk c: tile buf 0, staging set A
        STS_SET(0, xrA, zrA);
        __syncthreads();
        if (c + 2 < NCHUNK) LOAD_SET(xrA, zrA, (c + 2) * KC);
        MMA_PHASE(0);

        // odd chunk c+1: tile buf 1, staging set B
        STS_SET(1, xrB, zrB);
        __syncthreads();
        if (c + 3 < NCHUNK) LOAD_SET(xrB, zrB, (c + 3) * KC);
        MMA_PHASE(1);
    }

    // epilogue: write warp tile to g_partial[by][j][i]
    float* part = g_partial + (size_t)blockIdx.y * (KK * NN);
#pragma unroll
    for (int m = 0; m < 2; ++m) {
        const int i0 = ibase + wi + m * 16 + (lane >> 2);
#pragma unroll
        for (int n = 0; n < 4; ++n) {
            const int j0 = wj + n * 8 + (lane & 3) * 2;
            part[(size_t)j0 * NN + i0]           = acc[m][n][0];
            part[(size_t)(j0 + 1) * NN + i0]     = acc[m][n][1];
            part[(size_t)j0 * NN + i0 + 8]       = acc[m][n][2];
            part[(size_t)(j0 + 1) * NN + i0 + 8] = acc[m][n][3];
        }
    }

    // ---- fused finish: last split-CTA of this i-tile folds the loss ----
    __shared__ int s_last;
    __threadfence();                       // release partial stores
    __syncthreads();
    if (tid == 0) s_last = atomicAdd(&g_counter[blockIdx.x], 1);
    __syncthreads();
    if (s_last == KSPLIT - 1) {
        __threadfence();                   // acquire other CTAs' partial stores
        const float vn = *vn_p;
        float local = 0.f;
#pragma unroll 1
        for (int j = 0; j < (KK * MTILE) / 256; ++j) {   // 32 elems/thread
            const int e  = tid + j * 256;                // 0..8191
            const int k  = e >> 7;
            const int i  = ibase + (e & 127);
            float rs = 0.f;
#pragma unroll
            for (int s = 0; s < KSPLIT; ++s)
                rs += g_partial[(size_t)s * (KK * NN) + (size_t)k * NN + i];
            const float z   = zs[(size_t)k * NN + i];
            const float xd  = X[(size_t)i * NN + i];
            const float num = z * xd;
            local += num / (vn + rs - num);
        }
#pragma unroll
        for (int off = 16; off > 0; off >>= 1)
            local += __shfl_down_sync(0xffffffffu, local, off);
        __shared__ float red[8];
        if (lane == 0) red[wid] = local;
        __syncthreads();
        if (wid == 0) {
            float v = (lane < 8) ? red[lane] : 0.f;
#pragma unroll
            for (int off = 4; off > 0; off >>= 1)
                v += __shfl_down_sync(0xffffffffu, v, off);
            if (lane == 0) atomicAdd(out, -v / (float)KK);
        }
    }
}

// ---------------------------------------------------------------------------
extern "C" void kernel_launch(void* const* d_in, const int* in_sizes, int n_in,
                              void* d_out, int out_size) {
    const float* zs = (const float*)d_in[0];   // [64, 4096]
    const float* X  = (const float*)d_in[1];   // [4096, 4096]
    const float* vn = (const float*)d_in[2];   // scalar
    float* out = (float*)d_out;

    zero_kernel<<<1, 64>>>(out);
    dim3 grid(NTILES, KSPLIT);                 // 32 x 8 = 256 CTAs
    gemm_hmma<<<grid, 256>>>(zs, X, vn, out);
}

// round 15
// speedup vs baseline: 1.8530x; 1.3955x over previous
#include <cuda_runtime.h>
#include <cuda_bf16.h>
#include <cstdint>

#define KK 64
#define NN 4096
#define MTILE 128
#define KC 32                          // n-elements per chunk
#define KSPLIT 8
#define NCHUNK ((NN / KSPLIT) / KC)    // 16 (even)
#define SROW 40                        // smem row stride in bf16 elems (80 B)
#define NTILES (NN / MTILE)            // 32 i-tiles

// Accumulated row_sums: [KK][NN] fp32 = 1 MB (REDG-accumulated by split-CTAs)
__device__ float g_rowsum[KK * NN];

static __device__ __forceinline__ uint32_t smem_u32(const void* p) {
    uint32_t a;
    asm("{ .reg .u64 t; cvta.to.shared.u64 t, %1; cvt.u32.u64 %0, t; }"
        : "=r"(a) : "l"(p));
    return a;
}
static __device__ __forceinline__ uint32_t pack2(float a, float b) {
    __nv_bfloat162 h = __floats2bfloat162_rn(a, b);
    return *reinterpret_cast<uint32_t*>(&h);
}
static __device__ __forceinline__ void sts128(uint32_t a, uint32_t x, uint32_t y,
                                              uint32_t z, uint32_t w) {
    asm volatile("st.shared.v4.b32 [%0], {%1,%2,%3,%4};"
                 :: "r"(a), "r"(x), "r"(y), "r"(z), "r"(w) : "memory");
}
static __device__ __forceinline__ void ldsm4(uint32_t addr, uint32_t& r0, uint32_t& r1,
                                             uint32_t& r2, uint32_t& r3) {
    asm volatile("ldmatrix.sync.aligned.m8n8.x4.shared.b16 {%0,%1,%2,%3}, [%4];"
                 : "=r"(r0), "=r"(r1), "=r"(r2), "=r"(r3) : "r"(addr));
}
static __device__ __forceinline__ void mma16816(float& c0, float& c1, float& c2, float& c3,
                                                uint32_t a0, uint32_t a1, uint32_t a2,
                                                uint32_t a3, uint32_t b0, uint32_t b1) {
    asm volatile("mma.sync.aligned.m16n8k16.row.col.f32.bf16.bf16.f32 "
                 "{%0,%1,%2,%3}, {%4,%5,%6,%7}, {%8,%9}, {%0,%1,%2,%3};"
                 : "+f"(c0), "+f"(c1), "+f"(c2), "+f"(c3)
                 : "r"(a0), "r"(a1), "r"(a2), "r"(a3), "r"(b0), "r"(b1));
}
static __device__ __forceinline__ void redg_add(float* p, float v) {
    asm volatile("red.global.add.f32 [%0], %1;" :: "l"(p), "f"(v) : "memory");
}

// ---------------------------------------------------------------------------
// zero: out + row_sums buffer (grid-stride), runs before gemm each replay
// grid = 256 blocks x 256 threads; each thread clears 4 floats.
// ---------------------------------------------------------------------------
__global__ void zero_kernel(float* out) {
    const int idx = blockIdx.x * blockDim.x + threadIdx.x;
    if (idx == 0) out[0] = 0.f;
    float4 z4 = make_float4(0.f, 0.f, 0.f, 0.f);
    *(float4*)&g_rowsum[idx * 4] = z4;     // 65536 threads x 4 = 262144 floats
}

// ---------------------------------------------------------------------------
// HMMA GEMM: red.global.add into g_rowsum[k][i] (R11 mainloop, unchanged)
// grid = (32, KSPLIT) = 256 CTAs, block = 256 (8 warps: 4 i-groups x 2 k-groups)
// ---------------------------------------------------------------------------
__global__ __launch_bounds__(256, 2)
void gemm_hmma(const float* __restrict__ zs, const float* __restrict__ X) {
    __shared__ __align__(16) __nv_bfloat16 Xs[2][MTILE * SROW];
    __shared__ __align__(16) __nv_bfloat16 Zs[2][KK * SROW];

    const int tid   = threadIdx.x;
    const int lane  = tid & 31;
    const int wid   = tid >> 5;
    const int ibase = blockIdx.x * MTILE;
    const int nbase = blockIdx.y * (NN / KSPLIT);

    const uint32_t XsA[2] = { smem_u32(Xs[0]), smem_u32(Xs[1]) };
    const uint32_t ZsA[2] = { smem_u32(Zs[0]), smem_u32(Zs[1]) };

    // ---- producer assignments (8-float units) ----
    const int xu0 = tid, xu1 = tid + 256;
    const int xrow0 = xu0 >> 2, xqc0 = xu0 & 3;
    const int xrow1 = xu1 >> 2, xqc1 = xu1 & 3;
    const float* xp0 = X + (size_t)(ibase + xrow0) * NN + nbase + xqc0 * 8;
    const float* xp1 = X + (size_t)(ibase + xrow1) * NN + nbase + xqc1 * 8;
    const uint32_t xs0 = xrow0 * (SROW * 2) + xqc0 * 16;
    const uint32_t xs1 = xrow1 * (SROW * 2) + xqc1 * 16;
    const int zrow = tid >> 2, zqc = tid & 3;
    const float* zp = zs + (size_t)zrow * NN + nbase + zqc * 8;
    const uint32_t zsto = zrow * (SROW * 2) + zqc * 16;

    // ---- consumer (ldmatrix) address components ----
    const int wi = (wid & 3) * 32;
    const int wj = (wid >> 2) * 32;
    const uint32_t a_row = wi + (lane & 15);
    const uint32_t a_col16 = (lane >> 4);
    const uint32_t b_row = wj + ((lane >> 4) & 1) * 8 + (lane & 7);
    const uint32_t b_col16 = ((lane >> 3) & 1);

    float acc[2][4][4];
#pragma unroll
    for (int m = 0; m < 2; ++m)
#pragma unroll
        for (int n = 0; n < 4; ++n)
#pragma unroll
            for (int q = 0; q < 4; ++q) acc[m][n][q] = 0.f;

#define LOAD_SET(xr, zr, off)                                              \
    do {                                                                   \
        xr[0] = *(const float4*)(xp0 + (off));                             \
        xr[1] = *(const float4*)(xp0 + (off) + 4);                         \
        xr[2] = *(const float4*)(xp1 + (off));                             \
        xr[3] = *(const float4*)(xp1 + (off) + 4);                         \
        zr[0] = *(const float4*)(zp + (off));                              \
        zr[1] = *(const float4*)(zp + (off) + 4);                          \
    } while (0)

#define STS_SET(buf, xr, zr)                                                        \
    do {                                                                            \
        sts128(XsA[buf] + xs0, pack2(xr[0].x, xr[0].y), pack2(xr[0].z, xr[0].w),    \
               pack2(xr[1].x, xr[1].y), pack2(xr[1].z, xr[1].w));                   \
        sts128(XsA[buf] + xs1, pack2(xr[2].x, xr[2].y), pack2(xr[2].z, xr[2].w),    \
               pack2(xr[3].x, xr[3].y), pack2(xr[3].z, xr[3].w));                   \
        sts128(ZsA[buf] + zsto, pack2(zr[0].x, zr[0].y), pack2(zr[0].z, zr[0].w),   \
               pack2(zr[1].x, zr[1].y), pack2(zr[1].z, zr[1].w));                   \
    } while (0)

#define MMA_PHASE(buf)                                                              \
    do {                                                                            \
        _Pragma("unroll")                                                           \
        for (int s = 0; s < 2; ++s) {                                               \
            uint32_t a[2][4], b[2][4];                                              \
            _Pragma("unroll")                                                       \
            for (int h = 0; h < 2; ++h)                                             \
                ldsm4(XsA[buf] + (a_row + h * 16) * (SROW * 2) +                    \
                          (a_col16 + s * 2) * 16,                                   \
                      a[h][0], a[h][1], a[h][2], a[h][3]);                          \
            _Pragma("unroll")                                                       \
            for (int g = 0; g < 2; ++g)                                             \
                ldsm4(ZsA[buf] + (b_row + g * 16) * (SROW * 2) +                    \
                          (b_col16 + s * 2) * 16,                                   \
                      b[g][0], b[g][1], b[g][2], b[g][3]);                          \
            _Pragma("unroll")                                                       \
            for (int m = 0; m < 2; ++m)                                             \
                _Pragma("unroll")                                                   \
                for (int n = 0; n < 4; ++n) {                                       \
                    const int g = n >> 1, hi = (n & 1) * 2;                         \
                    mma16816(acc[m][n][0], acc[m][n][1], acc[m][n][2],              \
                             acc[m][n][3], a[m][0], a[m][1], a[m][2], a[m][3],      \
                             b[g][hi], b[g][hi + 1]);                               \
                }                                                                   \
        }                                                                           \
    } while (0)

    // prologue: stage chunks 0 (set A) and 1 (set B)
    float4 xrA[4], zrA[2], xrB[4], zrB[2];
    LOAD_SET(xrA, zrA, 0);
    LOAD_SET(xrB, zrB, KC);

#pragma unroll 1
    for (int c = 0; c < NCHUNK; c += 2) {
        // even chunk c: tile buf 0, staging set A
        STS_SET(0, xrA, zrA);
        __syncthreads();
        if (c + 2 < NCHUNK) LOAD_SET(xrA, zrA, (c + 2) * KC);
        MMA_PHASE(0);

        // odd chunk c+1: tile buf 1, staging set B
        STS_SET(1, xrB, zrB);
        __syncthreads();
        if (c + 3 < NCHUNK) LOAD_SET(xrB, zrB, (c + 3) * KC);
        MMA_PHASE(1);
    }

    // epilogue: accumulate warp tile into g_rowsum[j][i] via REDG (no return)
#pragma unroll
    for (int m = 0; m < 2; ++m) {
        const int i0 = ibase + wi + m * 16 + (lane >> 2);
#pragma unroll
        for (int n = 0; n < 4; ++n) {
            const int j0 = wj + n * 8 + (lane & 3) * 2;
            redg_add(&g_rowsum[(size_t)j0 * NN + i0],           acc[m][n][0]);
            redg_add(&g_rowsum[(size_t)(j0 + 1) * NN + i0],     acc[m][n][1]);
            redg_add(&g_rowsum[(size_t)j0 * NN + i0 + 8],       acc[m][n][2]);
            redg_add(&g_rowsum[(size_t)(j0 + 1) * NN + i0 + 8], acc[m][n][3]);
        }
    }
}

// ---------------------------------------------------------------------------
// finish: local = num/(vn+den) summed over [KK][NN]; out = -sum/KK
// reads row_sums 1 MB + zs 1 MB + diag -> ~1.3 us
// ---------------------------------------------------------------------------
__global__ __launch_bounds__(256)
void finish_kernel(const float* __restrict__ zs, const float* __restrict__ X,
                   const float* __restrict__ vn_p, float* __restrict__ out) {
    const int idx = blockIdx.x * blockDim.x + threadIdx.x;  // covers KK*NN exactly
    const float vn = *vn_p;
    const int i = idx & (NN - 1);

    const float rs  = g_rowsum[idx];
    const float z   = zs[idx];
    const float xd  = X[(size_t)i * NN + i];
    const float num = z * xd;
    const float den = rs - num;
    float local = num / (vn + den);

#pragma unroll
    for (int off = 16; off > 0; off >>= 1)
        local += __shfl_down_sync(0xffffffffu, local, off);

    __shared__ float red[8];
    const int lane = threadIdx.x & 31;
    const int wd   = threadIdx.x >> 5;
    if (lane == 0) red[wd] = local;
    __syncthreads();
    if (wd == 0) {
        float v = (lane < 8) ? red[lane] : 0.f;
#pragma unroll
        for (int off = 4; off > 0; off >>= 1)
            v += __shfl_down_sync(0xffffffffu, v, off);
        if (lane == 0) atomicAdd(out, -v / (float)KK);
    }
}

// ---------------------------------------------------------------------------
extern "C" void kernel_launch(void* const* d_in, const int* in_sizes, int n_in,
                              void* d_out, int out_size) {
    const float* zs = (const float*)d_in[0];   // [64, 4096]
    const float* X  = (const float*)d_in[1];   // [4096, 4096]
    const float* vn = (const float*)d_in[2];   // scalar
    float* out = (float*)d_out;

    zero_kernel<<<256, 256>>>(out);            // clears out + 1 MB row_sums
    dim3 grid(NTILES, KSPLIT);                 // 32 x 8 = 256 CTAs
    gemm_hmma<<<grid, 256>>>(zs, X);
    finish_kernel<<<(KK * NN) / 256, 256>>>(zs, X, vn, out);
}